// round 2
// baseline (speedup 1.0000x reference)
#include <cuda_runtime.h>

// Shapes (fixed):
//   W: [D=1024, ML=8192] row-major
//   b: [D=1024]
//   out: [B=4, S=4096, D=1024] = broadcast_B( W[:, :S].T + b )
#define B_DIM 4
#define S_DIM 4096
#define D_DIM 1024
#define ML_DIM 8192
#define S_CHUNK 8   // s columns per block

__device__ __forceinline__ float f4_get(const float4& v, int i) {
    return i == 0 ? v.x : (i == 1 ? v.y : (i == 2 ? v.z : v.w));
}

// One block = full D dimension (256 threads x 4 d each), S_CHUNK columns of s.
// Each thread: read 4 W rows as float4 along s (8 LDG.128, all independent),
// 4x4 register transpose, add bias, write coalesced float4 stores along d
// replicated over the 4 batch copies.
__global__ void __launch_bounds__(256)
posemb_regtrans_kernel(const float4* __restrict__ W4,
                       const float4* __restrict__ bias4,
                       float4* __restrict__ out4) {
    const int g  = threadIdx.x;          // d-group: d = 4g .. 4g+3
    const int s0 = blockIdx.x * S_CHUNK; // s chunk start

    const float4 b4 = bias4[g];

    // Stage all 8 loads first for max MLP.
    // r[j][h] = W[4g+j][s0+4h .. s0+4h+3]
    float4 r[4][2];
#pragma unroll
    for (int j = 0; j < 4; j++) {
        const size_t rowbase = (size_t)(4 * g + j) * (ML_DIM / 4) + (s0 >> 2);
#pragma unroll
        for (int h = 0; h < 2; h++) {
            r[j][h] = W4[rowbase + h];
        }
    }

    const size_t batch_stride = (size_t)S_DIM * (D_DIM / 4);  // in float4

#pragma unroll
    for (int h = 0; h < 2; h++) {
#pragma unroll
        for (int i = 0; i < 4; i++) {
            // 4x4 register transpose: output row s = s0 + 4h + i,
            // d components come from the i-th lane of each staged row.
            float4 v;
            v.x = f4_get(r[0][h], i) + b4.x;
            v.y = f4_get(r[1][h], i) + b4.y;
            v.z = f4_get(r[2][h], i) + b4.z;
            v.w = f4_get(r[3][h], i) + b4.w;

            const size_t base = (size_t)(s0 + 4 * h + i) * (D_DIM / 4) + g;
#pragma unroll
            for (int bb = 0; bb < B_DIM; bb++) {
                out4[(size_t)bb * batch_stride + base] = v;
            }
        }
    }
}

extern "C" void kernel_launch(void* const* d_in, const int* in_sizes, int n_in,
                              void* d_out, int out_size) {
    (void)in_sizes; (void)n_in; (void)out_size;
    const float4* W4    = (const float4*)d_in[1];
    const float4* bias4 = (const float4*)d_in[2];
    float4* out4        = (float4*)d_out;

    dim3 block(256);
    dim3 grid(S_DIM / S_CHUNK);  // 512 blocks
    posemb_regtrans_kernel<<<grid, block>>>(W4, bias4, out4);
}

// round 3
// speedup vs baseline: 1.2463x; 1.2463x over previous
#include <cuda_runtime.h>

// Shapes (fixed):
//   W: [D=1024, ML=8192] row-major
//   b: [D=1024]
//   out: [B=4, S=4096, D=1024] = broadcast_B( W[:, :S].T + b )
#define B_DIM 4
#define S_DIM 4096
#define D_DIM 1024
#define ML_DIM 8192

#define TSTRIDE 34  // 32 d + 2 pad: bank=(2s+d)%32 -> 2-way STS, conflict-free LDS.64

// Block: 256 threads. Covers d-tile of 32 and s-tile of 64 (two 32-s subtiles).
// Load:  thread (drow = t/8, s4 = t%8): LDG.128 W[d0+drow][s0+32u + 4*s4 ..+3]
//        scatter 4 STS.32 into tile_T[u][s][drow]  (2-way bank conflicts max)
// Store: thread (sl = t/8, dg = t%8): LDS.64 x2 -> float4 along d, +bias,
//        STG.128 x4 batches, fully coalesced.
__global__ void __launch_bounds__(256)
posemb_smem_v3(const float4* __restrict__ W4,
               const float4* __restrict__ bias4,
               float4* __restrict__ out4) {
    __shared__ float tile[2][32 * TSTRIDE];

    const int t  = threadIdx.x;
    const int s0 = blockIdx.x * 64;
    const int d0 = blockIdx.y * 32;

    const int drow = t >> 3;   // 0..31
    const int s4   = t & 7;    // 0..7

    // Two independent loads staged up front (MLP).
    const size_t rowbase = (size_t)(d0 + drow) * (ML_DIM / 4) + (s0 >> 2) + s4;
    const float4 w0 = W4[rowbase];        // s-subtile 0
    const float4 w1 = W4[rowbase + 8];    // s-subtile 1 (+32 s)

    const int sb = 4 * s4;
    tile[0][(sb + 0) * TSTRIDE + drow] = w0.x;
    tile[0][(sb + 1) * TSTRIDE + drow] = w0.y;
    tile[0][(sb + 2) * TSTRIDE + drow] = w0.z;
    tile[0][(sb + 3) * TSTRIDE + drow] = w0.w;
    tile[1][(sb + 0) * TSTRIDE + drow] = w1.x;
    tile[1][(sb + 1) * TSTRIDE + drow] = w1.y;
    tile[1][(sb + 2) * TSTRIDE + drow] = w1.z;
    tile[1][(sb + 3) * TSTRIDE + drow] = w1.w;

    __syncthreads();

    const int dg = t & 7;     // d float4-group (8 per 32-d tile)
    const int sl = t >> 3;    // 0..31

    const float4 bb = bias4[(d0 >> 2) + dg];
    const size_t batch_stride = (size_t)S_DIM * (D_DIM / 4);

#pragma unroll
    for (int u = 0; u < 2; u++) {
        const float* row = &tile[u][sl * TSTRIDE + 4 * dg];
        const float2 lo = *reinterpret_cast<const float2*>(row);
        const float2 hi = *reinterpret_cast<const float2*>(row + 2);

        float4 v;
        v.x = lo.x + bb.x;
        v.y = lo.y + bb.y;
        v.z = hi.x + bb.z;
        v.w = hi.y + bb.w;

        const size_t base = (size_t)(s0 + 32 * u + sl) * (D_DIM / 4) + (d0 >> 2) + dg;
#pragma unroll
        for (int bbt = 0; bbt < B_DIM; bbt++) {
            out4[(size_t)bbt * batch_stride + base] = v;
        }
    }
}

extern "C" void kernel_launch(void* const* d_in, const int* in_sizes, int n_in,
                              void* d_out, int out_size) {
    (void)in_sizes; (void)n_in; (void)out_size;
    const float4* W4    = (const float4*)d_in[1];
    const float4* bias4 = (const float4*)d_in[2];
    float4* out4        = (float4*)d_out;

    dim3 block(256);
    dim3 grid(S_DIM / 64, D_DIM / 32);  // 64 x 32 = 2048 blocks
    posemb_smem_v3<<<grid, block>>>(W4, bias4, out4);
}